// round 5
// baseline (speedup 1.0000x reference)
#include <cuda_runtime.h>
#include <cstdint>

#define SQRT2F     1.4142135623730951f
#define INVSQRT2F  0.7071067811865476f

using ull = unsigned long long;

__device__ __forceinline__ ull pack2(float lo, float hi) {
    ull r; asm("mov.b64 %0, {%1, %2};" : "=l"(r) : "f"(lo), "f"(hi)); return r;
}
__device__ __forceinline__ void unpack2(ull v, float& lo, float& hi) {
    asm("mov.b64 {%0, %1}, %2;" : "=f"(lo), "=f"(hi) : "l"(v));
}
__device__ __forceinline__ void fma2(ull& d, ull a, ull b) {
    asm("fma.rn.f32x2 %0, %1, %2, %0;" : "+l"(d) : "l"(a), "l"(b));
}

// ---------------- scratch (allowed: __device__ globals) ----------------
__device__ float g_out1[8 * 256 * 64 * 64];     // conv1 output (after lrelu)
__device__ float g_up[8 * 256 * 128 * 128];     // bilinear-upsampled conv1 output
__device__ float g_s64[8 * 128 * 64 * 64];      // 1x1 skip conv at 64x64
__device__ float g_w1T[256 * 256 * 9];          // [(ci*9+k)*256 + co], scaled
__device__ float g_w2T[256 * 9 * 128];          // [(ci*9+k)*128 + co], scaled
__device__ float g_wskT[256 * 128];             // [ci*128 + co], scaled

// ---------------- weight transpose + equalized-lr scale ----------------
__global__ void k_wt1(const float* __restrict__ w) {
    int idx = blockIdx.x * 256 + threadIdx.x;
    if (idx >= 256 * 256 * 9) return;
    int co = idx & 255; int r = idx >> 8;      // r = ci*9 + k
    int ci = r / 9;     int k = r - ci * 9;
    g_w1T[idx] = w[(co * 256 + ci) * 9 + k] * (1.0f / 48.0f);
}
__global__ void k_wt2(const float* __restrict__ w) {
    int idx = blockIdx.x * 256 + threadIdx.x;
    if (idx >= 128 * 256 * 9) return;
    int co = idx & 127; int r = idx >> 7;
    int ci = r / 9;     int k = r - ci * 9;
    g_w2T[idx] = w[(co * 256 + ci) * 9 + k] * (1.0f / 48.0f);
}
__global__ void k_wts(const float* __restrict__ w) {
    int idx = blockIdx.x * 256 + threadIdx.x;
    if (idx >= 256 * 128) return;
    int co = idx & 127; int ci = idx >> 7;
    g_wskT[idx] = w[co * 256 + ci] * (1.0f / 16.0f);
}

// ---------------- conv1: 3x3 256->256 @64x64, pad 1, + bias + lrelu*sqrt2 ----------------
// Block: 32 co x (8 rows x 32 cols). Threads 256: co_sub(8) x row(8) x colg(4).
// Thread: 4 co (2 f32x2 pairs) x 8 px.
__global__ void __launch_bounds__(256) k_conv1(const float* __restrict__ x,
                                               const float* __restrict__ b1) {
    const int n    = blockIdx.z >> 3;
    const int cot  = blockIdx.z & 7;
    const int row0 = blockIdx.y * 8;
    const int col0 = blockIdx.x * 32;
    const int tid  = threadIdx.x;
    const int co_sub = tid >> 5;          // warp id -> weight broadcast within warp
    const int row    = (tid >> 2) & 7;
    const int colg   = tid & 3;
    const int cobase = co_sub * 4;

    __shared__ __align__(16) float s_in[8][10][35];
    __shared__ __align__(16) float s_w[8][9][32];

    ull acc[2][8];
#pragma unroll
    for (int p = 0; p < 2; p++)
#pragma unroll
        for (int px = 0; px < 8; px++) acc[p][px] = 0ull;

    for (int ci0 = 0; ci0 < 256; ci0 += 8) {
        __syncthreads();
        // weights: s_w[ci][k][co] = g_w1T[(ci0+ci)*2304 + k*256 + cot*32 + co]
        for (int i = tid; i < 8 * 9 * 32; i += 256) {
            int ci_l = i / 288; int rem = i - ci_l * 288;
            int k = rem >> 5;   int co = rem & 31;
            ((float*)s_w)[i] = g_w1T[(ci0 + ci_l) * 2304 + k * 256 + cot * 32 + co];
        }
        // input patch with zero padding
        for (int i = tid; i < 8 * 10 * 34; i += 256) {
            int ci_l = i / 340; int rem = i - ci_l * 340;
            int r = rem / 34;   int c = rem - r * 34;
            int gr = row0 + r - 1, gc = col0 + c - 1;
            float v = 0.0f;
            if ((unsigned)gr < 64u && (unsigned)gc < 64u)
                v = x[((n * 256 + ci0 + ci_l) << 12) + (gr << 6) + gc];
            s_in[ci_l][r][c] = v;
        }
        __syncthreads();

#pragma unroll 1
        for (int ci = 0; ci < 8; ci++) {
#pragma unroll
            for (int ky = 0; ky < 3; ky++) {
                const float* rp = &s_in[ci][row + ky][colg * 8];
                ull ib[10];
#pragma unroll
                for (int c = 0; c < 10; c++) { float v = rp[c]; ib[c] = pack2(v, v); }
#pragma unroll
                for (int p = 0; p < 2; p++) {
                    const float* wb = &s_w[ci][ky * 3][cobase + 2 * p];
                    ull wk0 = *(const ull*)(wb);
                    ull wk1 = *(const ull*)(wb + 32);
                    ull wk2 = *(const ull*)(wb + 64);
#pragma unroll
                    for (int px = 0; px < 8; px++) {
                        fma2(acc[p][px], ib[px],     wk0);
                        fma2(acc[p][px], ib[px + 1], wk1);
                        fma2(acc[p][px], ib[px + 2], wk2);
                    }
                }
            }
        }
    }

    const int orow = row0 + row;
    const int ocol = col0 + colg * 8;
#pragma unroll
    for (int p = 0; p < 2; p++) {
        int co = cot * 32 + cobase + 2 * p;
        float bl = b1[co], bh = b1[co + 1];
#pragma unroll
        for (int px = 0; px < 8; px++) {
            float lo, hi; unpack2(acc[p][px], lo, hi);
            float v0 = lo + bl; v0 = (v0 >= 0.0f ? v0 : 0.2f * v0) * SQRT2F;
            float v1 = hi + bh; v1 = (v1 >= 0.0f ? v1 : 0.2f * v1) * SQRT2F;
            g_out1[((n * 256 + co)     << 12) + (orow << 6) + ocol + px] = v0;
            g_out1[((n * 256 + co + 1) << 12) + (orow << 6) + ocol + px] = v1;
        }
    }
}

// ---------------- bilinear 2x upsample (half-pixel centers, edge clamp) ----------------
__global__ void k_up256() {   // g_out1[.,.,64,64] -> g_up[.,.,128,128]
    int idx = blockIdx.x * 256 + threadIdx.x;   // exact count
    int v = idx & 127, u = (idx >> 7) & 127, nc = idx >> 14;
    int i = u >> 1, j = v >> 1;
    int r0, r1, c0, c1; float wr0, wr1, wc0, wc1;
    if (u & 1) { r0 = i; r1 = min(i + 1, 63); wr0 = 0.75f; wr1 = 0.25f; }
    else       { r0 = max(i - 1, 0); r1 = i;  wr0 = 0.25f; wr1 = 0.75f; }
    if (v & 1) { c0 = j; c1 = min(j + 1, 63); wc0 = 0.75f; wc1 = 0.25f; }
    else       { c0 = max(j - 1, 0); c1 = j;  wc0 = 0.25f; wc1 = 0.75f; }
    const float* b = g_out1 + (nc << 12);
    float val = wr0 * (wc0 * b[(r0 << 6) + c0] + wc1 * b[(r0 << 6) + c1])
              + wr1 * (wc0 * b[(r1 << 6) + c0] + wc1 * b[(r1 << 6) + c1]);
    g_up[idx] = val;
}

__global__ void k_up_skip(float* __restrict__ out) {  // g_s64 -> d_out (skip branch)
    int idx = blockIdx.x * 256 + threadIdx.x;
    int v = idx & 127, u = (idx >> 7) & 127, nc = idx >> 14;
    int i = u >> 1, j = v >> 1;
    int r0, r1, c0, c1; float wr0, wr1, wc0, wc1;
    if (u & 1) { r0 = i; r1 = min(i + 1, 63); wr0 = 0.75f; wr1 = 0.25f; }
    else       { r0 = max(i - 1, 0); r1 = i;  wr0 = 0.25f; wr1 = 0.75f; }
    if (v & 1) { c0 = j; c1 = min(j + 1, 63); wc0 = 0.75f; wc1 = 0.25f; }
    else       { c0 = max(j - 1, 0); c1 = j;  wc0 = 0.25f; wc1 = 0.75f; }
    const float* b = g_s64 + (nc << 12);
    float val = wr0 * (wc0 * b[(r0 << 6) + c0] + wc1 * b[(r0 << 6) + c1])
              + wr1 * (wc0 * b[(r1 << 6) + c0] + wc1 * b[(r1 << 6) + c1]);
    out[idx] = val;
}

// ---------------- skip 1x1 conv at 64x64 (256->128) ----------------
// Block: one n, 64 co (cot in {0,1}), 64 contiguous px. Thread: 4 co x 4 px.
__global__ void __launch_bounds__(256) k_skip(const float* __restrict__ x) {
    const int n = blockIdx.z, cot = blockIdx.y;
    const int px0 = blockIdx.x * 64;
    const int tid = threadIdx.x;
    const int co_sub = tid >> 4, pxg = tid & 15;
    const int cobase = co_sub * 4, pxb = pxg * 4;
    __shared__ __align__(16) float s_x[16][64];
    __shared__ __align__(16) float s_w[16][64];
    ull acc[2][4];
#pragma unroll
    for (int p = 0; p < 2; p++)
#pragma unroll
        for (int j = 0; j < 4; j++) acc[p][j] = 0ull;

    for (int ci0 = 0; ci0 < 256; ci0 += 16) {
        __syncthreads();
        for (int i = tid; i < 1024; i += 256) {
            int ci_l = i >> 6, p = i & 63;
            s_x[ci_l][p] = x[((n * 256 + ci0 + ci_l) << 12) + px0 + p];
            s_w[ci_l][p] = g_wskT[(ci0 + ci_l) * 128 + cot * 64 + p];
        }
        __syncthreads();
#pragma unroll 4
        for (int ci = 0; ci < 16; ci++) {
            ull w0 = *(const ull*)&s_w[ci][cobase];
            ull w1 = *(const ull*)&s_w[ci][cobase + 2];
#pragma unroll
            for (int j = 0; j < 4; j++) {
                float v = s_x[ci][pxb + j];
                ull vb = pack2(v, v);
                fma2(acc[0][j], vb, w0);
                fma2(acc[1][j], vb, w1);
            }
        }
    }
#pragma unroll
    for (int p = 0; p < 2; p++) {
        int co = cot * 64 + cobase + 2 * p;
#pragma unroll
        for (int j = 0; j < 4; j++) {
            float lo, hi; unpack2(acc[p][j], lo, hi);
            g_s64[((n * 128 + co)     << 12) + px0 + pxb + j] = lo;
            g_s64[((n * 128 + co + 1) << 12) + px0 + pxb + j] = hi;
        }
    }
}

// ---------------- conv2: 3x3 256->128 @128x128 on g_up + lrelu + combine ----------------
__global__ void __launch_bounds__(256) k_conv2(const float* __restrict__ b2,
                                               float* __restrict__ out) {
    const int n    = blockIdx.z >> 2;
    const int cot  = blockIdx.z & 3;
    const int row0 = blockIdx.y * 8;
    const int col0 = blockIdx.x * 32;
    const int tid  = threadIdx.x;
    const int co_sub = tid >> 5;
    const int row    = (tid >> 2) & 7;
    const int colg   = tid & 3;
    const int cobase = co_sub * 4;

    __shared__ __align__(16) float s_in[8][10][35];
    __shared__ __align__(16) float s_w[8][9][32];

    ull acc[2][8];
#pragma unroll
    for (int p = 0; p < 2; p++)
#pragma unroll
        for (int px = 0; px < 8; px++) acc[p][px] = 0ull;

    for (int ci0 = 0; ci0 < 256; ci0 += 8) {
        __syncthreads();
        for (int i = tid; i < 8 * 9 * 32; i += 256) {
            int ci_l = i / 288; int rem = i - ci_l * 288;
            int k = rem >> 5;   int co = rem & 31;
            ((float*)s_w)[i] = g_w2T[(ci0 + ci_l) * 1152 + k * 128 + cot * 32 + co];
        }
        for (int i = tid; i < 8 * 10 * 34; i += 256) {
            int ci_l = i / 340; int rem = i - ci_l * 340;
            int r = rem / 34;   int c = rem - r * 34;
            int gr = row0 + r - 1, gc = col0 + c - 1;
            float v = 0.0f;
            if ((unsigned)gr < 128u && (unsigned)gc < 128u)
                v = g_up[((n * 256 + ci0 + ci_l) << 14) + (gr << 7) + gc];
            s_in[ci_l][r][c] = v;
        }
        __syncthreads();

#pragma unroll 1
        for (int ci = 0; ci < 8; ci++) {
#pragma unroll
            for (int ky = 0; ky < 3; ky++) {
                const float* rp = &s_in[ci][row + ky][colg * 8];
                ull ib[10];
#pragma unroll
                for (int c = 0; c < 10; c++) { float v = rp[c]; ib[c] = pack2(v, v); }
#pragma unroll
                for (int p = 0; p < 2; p++) {
                    const float* wb = &s_w[ci][ky * 3][cobase + 2 * p];
                    ull wk0 = *(const ull*)(wb);
                    ull wk1 = *(const ull*)(wb + 32);
                    ull wk2 = *(const ull*)(wb + 64);
#pragma unroll
                    for (int px = 0; px < 8; px++) {
                        fma2(acc[p][px], ib[px],     wk0);
                        fma2(acc[p][px], ib[px + 1], wk1);
                        fma2(acc[p][px], ib[px + 2], wk2);
                    }
                }
            }
        }
    }

    const int orow = row0 + row;
    const int ocol = col0 + colg * 8;
#pragma unroll
    for (int p = 0; p < 2; p++) {
        int co = cot * 32 + cobase + 2 * p;
        float bl = b2[co], bh = b2[co + 1];
#pragma unroll
        for (int px = 0; px < 8; px++) {
            float lo, hi; unpack2(acc[p][px], lo, hi);
            float v0 = lo + bl; v0 = (v0 >= 0.0f ? v0 : 0.2f * v0) * SQRT2F;
            float v1 = hi + bh; v1 = (v1 >= 0.0f ? v1 : 0.2f * v1) * SQRT2F;
            int i0 = ((n * 128 + co)     << 14) + (orow << 7) + ocol + px;
            int i1 = ((n * 128 + co + 1) << 14) + (orow << 7) + ocol + px;
            out[i0] = (v0 + out[i0]) * INVSQRT2F;
            out[i1] = (v1 + out[i1]) * INVSQRT2F;
        }
    }
}

// ---------------- launch ----------------
extern "C" void kernel_launch(void* const* d_in, const int* in_sizes, int n_in,
                              void* d_out, int out_size) {
    const float* x   = (const float*)d_in[0];
    const float* w1  = (const float*)d_in[1];
    const float* b1  = (const float*)d_in[2];
    const float* w2  = (const float*)d_in[3];
    const float* b2  = (const float*)d_in[4];
    const float* wsk = (const float*)d_in[5];
    float* out = (float*)d_out;

    k_wt1<<<2304, 256>>>(w1);
    k_wt2<<<1152, 256>>>(w2);
    k_wts<<<128, 256>>>(wsk);

    k_conv1<<<dim3(2, 8, 64), 256>>>(x, b1);          // 64 cols/32, 64 rows/8, 8n*8cot
    k_up256<<<131072, 256>>>();                       // 8*256*128*128 elems
    k_skip<<<dim3(64, 2, 8), 256>>>(x);               // 4096/64 px tiles, 2 cot, 8 n
    k_up_skip<<<65536, 256>>>(out);                   // 8*128*128*128 elems -> d_out
    k_conv2<<<dim3(4, 16, 32), 256>>>(b2, out);       // 128/32, 128/8, 8n*4cot
}

// round 7
// speedup vs baseline: 2.4892x; 2.4892x over previous
#include <cuda_runtime.h>
#include <cstdint>

#define SQRT2F     1.4142135623730951f
#define INVSQRT2F  0.7071067811865476f

using u32 = uint32_t; using u64 = uint64_t; using ull = unsigned long long;

// ======================= helpers =======================
__device__ __forceinline__ ull pack2(float lo, float hi) {
    ull r; asm("mov.b64 %0, {%1, %2};" : "=l"(r) : "f"(lo), "f"(hi)); return r;
}
__device__ __forceinline__ void unpack2(ull v, float& lo, float& hi) {
    asm("mov.b64 {%0, %1}, %2;" : "=f"(lo), "=f"(hi) : "l"(v));
}
__device__ __forceinline__ void fma2(ull& d, ull a, ull b) {
    asm("fma.rn.f32x2 %0, %1, %2, %0;" : "+l"(d) : "l"(a), "l"(b));
}
__device__ __forceinline__ u32 f2tf32(float f) {
    u32 r; asm("cvt.rna.tf32.f32 %0, %1;" : "=r"(r) : "f"(f)); return r;
}
__device__ __forceinline__ void mma_tf32(float* c, const u32* a, const u32* b) {
    asm volatile("mma.sync.aligned.m16n8k8.row.col.f32.tf32.tf32.f32 "
                 "{%0,%1,%2,%3}, {%4,%5,%6,%7}, {%8,%9}, {%0,%1,%2,%3};"
                 : "+f"(c[0]), "+f"(c[1]), "+f"(c[2]), "+f"(c[3])
                 : "r"(a[0]), "r"(a[1]), "r"(a[2]), "r"(a[3]),
                   "r"(b[0]), "r"(b[1]));
}

// ======================= scratch =======================
__device__ float g_p1[8 * 256 * 66 * 66];        // padded conv1 input (border stays 0)
__device__ float g_out1[8 * 256 * 64 * 64];      // conv1 output (after lrelu)
__device__ float g_up_pad[8 * 256 * 130 * 130];  // padded upsampled conv1 output (border 0)
__device__ float g_s64[8 * 128 * 64 * 64];       // 1x1 skip conv at 64x64
__device__ u32   g_wB1[2 * 72 * 4096];           // conv1 wts tf32: [cot][chunk][k=32][co=128]
__device__ u32   g_wB2[72 * 4096];               // conv2 wts tf32: [chunk][k=32][co=128]
__device__ float g_wskT[256 * 128];              // skip weights [ci][co], scaled

// ======================= weight prep =======================
__global__ void k_wt1(const float* __restrict__ w) {
    int idx = blockIdx.x * 256 + threadIdx.x;        // 2*72*32*128 = 589824
    if (idx >= 589824) return;
    int co_l  = idx & 127;
    int k_l   = (idx >> 7) & 31;
    int chunk = idx >> 12;                            // 0..143
    int cot = chunk / 72, i = chunk % 72;
    int koff = i >> 3, cic = i & 7;
    int co = cot * 128 + co_l;
    int ci = cic * 32 + k_l;
    g_wB1[idx] = f2tf32(w[(co * 256 + ci) * 9 + koff] * (1.0f / 48.0f));
}
__global__ void k_wt2(const float* __restrict__ w) {
    int idx = blockIdx.x * 256 + threadIdx.x;        // 72*32*128 = 294912
    if (idx >= 294912) return;
    int co_l = idx & 127;
    int k_l  = (idx >> 7) & 31;
    int i    = idx >> 12;                             // 0..71
    int koff = i >> 3, cic = i & 7;
    int ci = cic * 32 + k_l;
    g_wB2[idx] = f2tf32(w[(co_l * 256 + ci) * 9 + koff] * (1.0f / 48.0f));
}
__global__ void k_wts(const float* __restrict__ w) {
    int idx = blockIdx.x * 256 + threadIdx.x;
    if (idx >= 256 * 128) return;
    int co = idx & 127; int ci = idx >> 7;
    g_wskT[idx] = w[co * 256 + ci] * (1.0f / 16.0f);
}

// ======================= pad x into g_p1 =======================
__global__ void k_pad1(const float* __restrict__ x) {
    int idx = blockIdx.x * 256 + threadIdx.x;        // 8*256*64*64
    int c = idx & 63, r = (idx >> 6) & 63, nc = idx >> 12;
    g_p1[(size_t)nc * 4356 + (r + 1) * 66 + (c + 1)] = x[idx];
}

// ======================= mma.sync tf32 implicit-GEMM conv (3x3, pad 1) =================
// CONV=1: in=g_p1 (66x66 pad), out 64x64, M-tile = 2 rows x 64 cols, cot {0,1} -> g_out1
// CONV=2: in=g_up_pad (130x130 pad), out 128x128, M-tile = 1 row x 128 cols -> combine d_out
template <int CONV>
__global__ void __launch_bounds__(256, 2) k_conv_mma(const float* __restrict__ bias,
                                                     float* __restrict__ dout) {
    constexpr int PW  = (CONV == 1) ? 66 : 130;
    constexpr int PSZ = PW * PW;
    constexpr int OW  = (CONV == 1) ? 64 : 128;
    constexpr int ROWS = 128 / OW;

    const int tile = blockIdx.x;
    const int cot  = blockIdx.y;
    const int n    = blockIdx.z;
    const int tid  = threadIdx.x;
    const int wid  = tid >> 5;
    const int lane = tid & 31;
    const int warp_m = wid >> 1;       // 0..3
    const int warp_n = wid & 1;        // 0..1
    const int lg = lane >> 2;          // 0..7
    const int lt = lane & 3;           // 0..3

    const float* in = (CONV == 1) ? g_p1 : g_up_pad;
    const u32* wB = ((CONV == 1) ? g_wB1 + cot * 72 * 4096 : g_wB2);

    __shared__ u32 sA[32][136];
    __shared__ u32 sB[32][136];

    // this thread's A-load pixel
    const int px = tid & 127;
    const int rl = (CONV == 1) ? (px >> 6) : 0;
    const int c  = px & (OW - 1);
    const int r0 = tile * ROWS;
    const int cihalf = tid >> 7;                 // 0..1

    float acc[2][8][4];
#pragma unroll
    for (int mt = 0; mt < 2; mt++)
#pragma unroll
        for (int nt = 0; nt < 8; nt++)
#pragma unroll
            for (int q = 0; q < 4; q++) acc[mt][nt][q] = 0.0f;

    for (int i = 0; i < 72; i++) {
        const int koff = i >> 3, cic = i & 7;
        const int ky = koff / 3, kx = koff - ky * 3;

        __syncthreads();
        // ---- B tile: 16KB straight copy ----
        {
            const uint4* src = (const uint4*)(wB + i * 4096);
#pragma unroll
            for (int p = 0; p < 4; p++) {
                uint4 v = src[p * 256 + tid];
                int lin = (p * 256 + tid) << 2;
                *(uint4*)&sB[lin >> 7][lin & 127] = v;
            }
        }
        // ---- A tile: 128 px x 32 ci ----
        {
            const float* ap = in + ((size_t)(n * 256 + cic * 32 + cihalf)) * PSZ
                                 + (size_t)(r0 + rl + ky) * PW + (c + kx);
            u32* sp = &sA[cihalf][px];
#pragma unroll
            for (int p = 0; p < 16; p++) {
                *sp = f2tf32(*ap);
                ap += 2 * PSZ;
                sp += 2 * 136;
            }
        }
        __syncthreads();

        // ---- compute: 4 k-steps of 8 ----
#pragma unroll
        for (int ks = 0; ks < 4; ks++) {
            const int kc = ks * 8 + lt;
            const int rb = warp_m * 32 + lg;
            u32 a[2][4];
#pragma unroll
            for (int mt = 0; mt < 2; mt++) {
                a[mt][0] = sA[kc][rb + mt * 16];
                a[mt][1] = sA[kc][rb + mt * 16 + 8];
                a[mt][2] = sA[kc + 4][rb + mt * 16];
                a[mt][3] = sA[kc + 4][rb + mt * 16 + 8];
            }
            const int nb = warp_n * 64 + lg;
            u32 b[8][2];
#pragma unroll
            for (int nt = 0; nt < 8; nt++) {
                b[nt][0] = sB[kc][nb + nt * 8];
                b[nt][1] = sB[kc + 4][nb + nt * 8];
            }
#pragma unroll
            for (int mt = 0; mt < 2; mt++)
#pragma unroll
                for (int nt = 0; nt < 8; nt++)
                    mma_tf32(acc[mt][nt], a[mt], b[nt]);
        }
    }

    // ---- epilogue: bias + leaky-relu (+ combine for conv2) ----
#pragma unroll
    for (int mt = 0; mt < 2; mt++) {
        const int p0 = warp_m * 32 + mt * 16 + lg;    // px of c0/c1
        const int p1 = p0 + 8;                         // px of c2/c3
        const int or0 = r0 + (p0 >> (CONV == 1 ? 6 : 7));
        const int oc0 = p0 & (OW - 1);
        const int or1 = r0 + (p1 >> (CONV == 1 ? 6 : 7));
        const int oc1 = p1 & (OW - 1);
#pragma unroll
        for (int nt = 0; nt < 8; nt++) {
            const int co = cot * 128 + warp_n * 64 + nt * 8 + lt * 2;
            const float bv0 = bias[co], bv1 = bias[co + 1];
            float v00 = acc[mt][nt][0] + bv0;  v00 = (v00 >= 0.0f ? v00 : 0.2f * v00) * SQRT2F;
            float v01 = acc[mt][nt][1] + bv1;  v01 = (v01 >= 0.0f ? v01 : 0.2f * v01) * SQRT2F;
            float v10 = acc[mt][nt][2] + bv0;  v10 = (v10 >= 0.0f ? v10 : 0.2f * v10) * SQRT2F;
            float v11 = acc[mt][nt][3] + bv1;  v11 = (v11 >= 0.0f ? v11 : 0.2f * v11) * SQRT2F;
            if (CONV == 1) {
                g_out1[((size_t)(n * 256 + co)     << 12) + (or0 << 6) + oc0] = v00;
                g_out1[((size_t)(n * 256 + co + 1) << 12) + (or0 << 6) + oc0] = v01;
                g_out1[((size_t)(n * 256 + co)     << 12) + (or1 << 6) + oc1] = v10;
                g_out1[((size_t)(n * 256 + co + 1) << 12) + (or1 << 6) + oc1] = v11;
            } else {
                size_t o00 = ((size_t)(n * 128 + co)     << 14) + (or0 << 7) + oc0;
                size_t o01 = ((size_t)(n * 128 + co + 1) << 14) + (or0 << 7) + oc0;
                size_t o10 = ((size_t)(n * 128 + co)     << 14) + (or1 << 7) + oc1;
                size_t o11 = ((size_t)(n * 128 + co + 1) << 14) + (or1 << 7) + oc1;
                dout[o00] = (v00 + dout[o00]) * INVSQRT2F;
                dout[o01] = (v01 + dout[o01]) * INVSQRT2F;
                dout[o10] = (v10 + dout[o10]) * INVSQRT2F;
                dout[o11] = (v11 + dout[o11]) * INVSQRT2F;
            }
        }
    }
}

// ======================= bilinear 2x upsample (half-pixel, edge clamp) =================
__global__ void k_up256() {   // g_out1[.,.,64,64] -> g_up_pad interior [130x130]
    int idx = blockIdx.x * 256 + threadIdx.x;
    int v = idx & 127, u = (idx >> 7) & 127, nc = idx >> 14;
    int i = u >> 1, j = v >> 1;
    int r0, r1, c0, c1; float wr0, wr1, wc0, wc1;
    if (u & 1) { r0 = i; r1 = min(i + 1, 63); wr0 = 0.75f; wr1 = 0.25f; }
    else       { r0 = max(i - 1, 0); r1 = i;  wr0 = 0.25f; wr1 = 0.75f; }
    if (v & 1) { c0 = j; c1 = min(j + 1, 63); wc0 = 0.75f; wc1 = 0.25f; }
    else       { c0 = max(j - 1, 0); c1 = j;  wc0 = 0.25f; wc1 = 0.75f; }
    const float* b = g_out1 + ((size_t)nc << 12);
    float val = wr0 * (wc0 * b[(r0 << 6) + c0] + wc1 * b[(r0 << 6) + c1])
              + wr1 * (wc0 * b[(r1 << 6) + c0] + wc1 * b[(r1 << 6) + c1]);
    g_up_pad[(size_t)nc * 16900 + (u + 1) * 130 + (v + 1)] = val;
}

__global__ void k_up_skip(float* __restrict__ out) {  // g_s64 -> d_out (skip branch)
    int idx = blockIdx.x * 256 + threadIdx.x;
    int v = idx & 127, u = (idx >> 7) & 127, nc = idx >> 14;
    int i = u >> 1, j = v >> 1;
    int r0, r1, c0, c1; float wr0, wr1, wc0, wc1;
    if (u & 1) { r0 = i; r1 = min(i + 1, 63); wr0 = 0.75f; wr1 = 0.25f; }
    else       { r0 = max(i - 1, 0); r1 = i;  wr0 = 0.25f; wr1 = 0.75f; }
    if (v & 1) { c0 = j; c1 = min(j + 1, 63); wc0 = 0.75f; wc1 = 0.25f; }
    else       { c0 = max(j - 1, 0); c1 = j;  wc0 = 0.25f; wc1 = 0.75f; }
    const float* b = g_s64 + ((size_t)nc << 12);
    float val = wr0 * (wc0 * b[(r0 << 6) + c0] + wc1 * b[(r0 << 6) + c1])
              + wr1 * (wc0 * b[(r1 << 6) + c0] + wc1 * b[(r1 << 6) + c1]);
    out[idx] = val;
}

// ======================= skip 1x1 conv at 64x64 (256->128), fp32 f32x2 =================
__global__ void __launch_bounds__(256) k_skip(const float* __restrict__ x) {
    const int n = blockIdx.z, cot = blockIdx.y;
    const int px0 = blockIdx.x * 64;
    const int tid = threadIdx.x;
    const int co_sub = tid >> 4, pxg = tid & 15;
    const int cobase = co_sub * 4, pxb = pxg * 4;
    __shared__ __align__(16) float s_x[16][64];
    __shared__ __align__(16) float s_w[16][64];
    ull acc[2][4];
#pragma unroll
    for (int p = 0; p < 2; p++)
#pragma unroll
        for (int j = 0; j < 4; j++) acc[p][j] = 0ull;

    for (int ci0 = 0; ci0 < 256; ci0 += 16) {
        __syncthreads();
        for (int i = tid; i < 1024; i += 256) {
            int ci_l = i >> 6, p = i & 63;
            s_x[ci_l][p] = x[((n * 256 + ci0 + ci_l) << 12) + px0 + p];
            s_w[ci_l][p] = g_wskT[(ci0 + ci_l) * 128 + cot * 64 + p];
        }
        __syncthreads();
#pragma unroll 4
        for (int ci = 0; ci < 16; ci++) {
            ull w0 = *(const ull*)&s_w[ci][cobase];
            ull w1 = *(const ull*)&s_w[ci][cobase + 2];
#pragma unroll
            for (int j = 0; j < 4; j++) {
                float v = s_x[ci][pxb + j];
                ull vb = pack2(v, v);
                fma2(acc[0][j], vb, w0);
                fma2(acc[1][j], vb, w1);
            }
        }
    }
#pragma unroll
    for (int p = 0; p < 2; p++) {
        int co = cot * 64 + cobase + 2 * p;
#pragma unroll
        for (int j = 0; j < 4; j++) {
            float lo, hi; unpack2(acc[p][j], lo, hi);
            g_s64[((n * 128 + co)     << 12) + px0 + pxb + j] = lo;
            g_s64[((n * 128 + co + 1) << 12) + px0 + pxb + j] = hi;
        }
    }
}

// ======================= launch =======================
extern "C" void kernel_launch(void* const* d_in, const int* in_sizes, int n_in,
                              void* d_out, int out_size) {
    const float* x   = (const float*)d_in[0];
    const float* w1  = (const float*)d_in[1];
    const float* b1  = (const float*)d_in[2];
    const float* w2  = (const float*)d_in[3];
    const float* b2  = (const float*)d_in[4];
    const float* wsk = (const float*)d_in[5];
    float* out = (float*)d_out;

    k_wt1<<<2304, 256>>>(w1);
    k_wt2<<<1152, 256>>>(w2);
    k_wts<<<128, 256>>>(wsk);
    k_pad1<<<32768, 256>>>(x);

    k_conv_mma<1><<<dim3(32, 2, 8), 256>>>(b1, nullptr);   // 32 row-tiles, 2 cot, 8 n
    k_up256<<<131072, 256>>>();                            // -> padded g_up_pad
    k_skip<<<dim3(64, 2, 8), 256>>>(x);
    k_up_skip<<<65536, 256>>>(out);                        // skip into d_out
    k_conv_mma<2><<<dim3(128, 1, 8), 256>>>(b2, out);      // 128 rows, 1 cot, 8 n
}